// round 9
// baseline (speedup 1.0000x reference)
#include <cuda_runtime.h>
#include <cuda_fp16.h>

// Residual VQ (L=8, G=2, K=1024, D=256), B=16, T=4096, N=65536.
// Single fp16 mma.sync GEMM (e pre-scaled by 1024 to avoid fp16 subnormals)
// -> approx distances; sound margin -> top-8 candidates -> exact fp32
// reference-semantics rescore (sequential d-ascending FMA chain,
// d = fl(fl(a+b)-2c), first-index argmin). STE/loss/outputs proven earlier.

#define LL 8
#define GG 2
#define KK 1024
#define DD 256
#define TT 4096
#define NTOK 65536ull
#define TILE 64
#define NTH 256
#define APITCH 264      // fp16 per A row (256 + 8 pad) -> 528B
#define BPITCH 72       // fp16 per B row (64 + 8 pad)  -> 144B
#define BSTAGE 18432    // 128 * BPITCH * 2
#define DPITCH 130      // fp32 per Dmat row

#define QOUT_ELEMS 33554432ull
#define LOSS_OFF   33554432ull
#define IDX_OFF    33554433ull

#define CBELEMS (LL * GG * KK * DD)

// smem byte offsets
#define OFF_X    0          // fp32 [256][64]   65536
#define OFF_AH   65536      // fp16 [64][264]   33792
#define OFF_B    99328      // 2 x BSTAGE       36864
#define OFF_DM   136192     // fp32 [64][130]   33280
#define OFF_E2S  169472     // fp32 [128]
#define OFF_ASM  169984     // fp32 [64]
#define OFF_RUNI 170240     // int  [64]
#define OFF_RED  170496     // double [256]
#define SMEM_TOT 172544

__device__ float   g_e2[LL * GG * KK];
__device__ double  g_loss[2048];
__device__ __half  g_eh[CBELEMS];     // fl16(1024 * e)

// ---------------------------------------------------------------- asm helpers
__device__ __forceinline__ void mma16816h(float* c, const unsigned* a, const unsigned* b) {
    asm volatile(
        "mma.sync.aligned.m16n8k16.row.col.f32.f16.f16.f32 "
        "{%0,%1,%2,%3},{%4,%5,%6,%7},{%8,%9},{%0,%1,%2,%3};"
        : "+f"(c[0]), "+f"(c[1]), "+f"(c[2]), "+f"(c[3])
        : "r"(a[0]), "r"(a[1]), "r"(a[2]), "r"(a[3]), "r"(b[0]), "r"(b[1]));
}
__device__ __forceinline__ void ldsm_x4(unsigned* r, unsigned addr) {
    asm volatile("ldmatrix.sync.aligned.m8n8.x4.shared.b16 {%0,%1,%2,%3},[%4];"
                 : "=r"(r[0]), "=r"(r[1]), "=r"(r[2]), "=r"(r[3]) : "r"(addr));
}
__device__ __forceinline__ void ldsm_x2(unsigned* r, unsigned addr) {
    asm volatile("ldmatrix.sync.aligned.m8n8.x2.shared.b16 {%0,%1},[%2];"
                 : "=r"(r[0]), "=r"(r[1]) : "r"(addr));
}
__device__ __forceinline__ void cpasync16(unsigned dst, const void* src) {
    asm volatile("cp.async.cg.shared.global [%0], [%1], 16;"
                 :: "r"(dst), "l"(__cvta_generic_to_global(src)));
}

// ---------------------------------------------------------------- ||e||^2 (exact ref rounding)
__global__ void e2_kernel(const float* __restrict__ cb) {
    int c = blockIdx.x * blockDim.x + threadIdx.x;
    if (c >= LL * GG * KK) return;
    const float* e = cb + (size_t)c * DD;
    float s = 0.0f;
    for (int d = 0; d < DD; ++d) {
        float v = e[d];
        s = __fadd_rn(s, __fmul_rn(v, v));
    }
    g_e2[c] = s;
}

// ---------------------------------------------------------------- codebook fp16 (scaled 1024x)
__global__ void eh_kernel(const float* __restrict__ cb) {
    int i = blockIdx.x * blockDim.x + threadIdx.x;
    if (i >= CBELEMS) return;
    g_eh[i] = __float2half_rn(__fmul_rn(cb[i], 1024.0f));
}

// ---------------------------------------------------------------- main
__global__ void __launch_bounds__(NTH, 1)
rvq_kernel(const float* __restrict__ xin, const float* __restrict__ cb,
           float* __restrict__ dout, unsigned long long out_size) {
    extern __shared__ char smraw[];
    float*   X    = (float*)(smraw + OFF_X);
    __half*  Ah   = (__half*)(smraw + OFF_AH);
    float*   DM   = (float*)(smraw + OFF_DM);
    float*   E2s  = (float*)(smraw + OFF_E2S);
    float*   Asm  = (float*)(smraw + OFF_ASM);
    int*     RUNI = (int*)(smraw + OFF_RUNI);
    double*  red  = (double*)(smraw + OFF_RED);

    const unsigned smbase = (unsigned)__cvta_generic_to_shared(smraw);
    const unsigned uB[2] = {smbase + OFF_B, smbase + OFF_B + BSTAGE};

    const int tid  = threadIdx.x;
    const int lane = tid & 31;
    const int warp = tid >> 5;
    const int wm   = warp >> 2;           // 0..1  (32 token rows)
    const int wn   = warp & 3;            // 0..3  (32 code cols)
    const int r4   = lane >> 2;           // 0..7
    const int kq   = lane & 3;            // 0..3

    // ldmatrix lane address components (verified bit-identical in round 7)
    const int lrowA  = (lane & 7) + (((lane >> 3) & 1) << 3);
    const int lkoffA = (lane >> 4) << 3;
    const unsigned aBase = smbase + OFF_AH +
        (unsigned)(((wm * 32 + lrowA) * APITCH + lkoffA) << 1);
    const int rB   = lane & 7;
    const int selB = (lane >> 3) & 1;
    const unsigned bLaneOff = (unsigned)(((wn * 32 + rB) * BPITCH + selB * 8) << 1);

    const int g    = blockIdx.y;
    const int tile = blockIdx.x;
    const int b    = tile >> 6;
    const int t0   = (tile & 63) << 6;
    const float* xb = xin + ((size_t)b * (GG * DD) + (size_t)g * DD) * TT + t0;

    for (int i = tid; i < DD * TILE; i += NTH) {
        int d = i >> 6, t = i & 63;
        X[i] = xb[(size_t)d * TT + t];
    }
    __syncthreads();

    double lacc = 0.0;

    for (int l = 0; l < LL; ++l) {
        const int    cbase = (l * GG + g) * KK;
        const float* cbl   = cb + (size_t)cbase * DD;

        // exact a_n = sequential fl(x^2) sum, d ascending (ref reduce order)
        if (tid < TILE) {
            float s = 0.0f;
            const float* xc = X + tid;
#pragma unroll 8
            for (int d = 0; d < DD; ++d) {
                float v = xc[d * TILE];
                s = __fadd_rn(s, __fmul_rn(v, v));
            }
            Asm[tid] = s;
        }
        // residual -> fp16 A
        for (int i = tid; i < DD * TILE; i += NTH) {
            int d = i >> 6, t = i & 63;
            Ah[t * APITCH + d] = __float2half_rn(X[d * TILE + t]);
        }
        __syncthreads();

        // per-token running top-8 (registers, tid<64)
        float v0 = 3.0e38f, v1 = 3.0e38f, v2 = 3.0e38f, v3 = 3.0e38f,
              v4 = 3.0e38f, v5 = 3.0e38f, v6 = 3.0e38f, v7 = 3.0e38f;
        int   i0 = 0, i1 = 0, i2 = 0, i3 = 0, i4 = 0, i5 = 0, i6 = 0, i7 = 0;

        for (int kb = 0; kb < 8; ++kb) {               // 8 blocks of 128 codes
            const size_t gbBlk = ((size_t)(cbase + kb * 128)) * DD;
            if (tid < 128) E2s[tid] = g_e2[cbase + kb * 128 + tid];

            // issue chunk 0 into stage 0
            {
                const __half* sH = g_eh + gbBlk;
#pragma unroll
                for (int it = 0; it < 4; ++it) {
                    int v = tid + it * NTH;
                    int code = v >> 3, d8 = (v & 7) * 8;
                    cpasync16(uB[0] + (unsigned)((code * BPITCH + d8) << 1),
                              sH + (size_t)code * DD + d8);
                }
                asm volatile("cp.async.commit_group;");
            }

            float acc[2][4][4];
#pragma unroll
            for (int mt = 0; mt < 2; ++mt)
#pragma unroll
                for (int nt = 0; nt < 4; ++nt)
#pragma unroll
                    for (int e = 0; e < 4; ++e) acc[mt][nt][e] = 0.f;

#pragma unroll 1
            for (int kc = 0; kc < 4; ++kc) {           // 4 d-chunks of 64
                if (kc < 3) {                          // prefetch next chunk
                    const __half* sH = g_eh + gbBlk + (kc + 1) * 64;
                    unsigned dh = uB[(kc + 1) & 1];
#pragma unroll
                    for (int it = 0; it < 4; ++it) {
                        int v = tid + it * NTH;
                        int code = v >> 3, d8 = (v & 7) * 8;
                        cpasync16(dh + (unsigned)((code * BPITCH + d8) << 1),
                                  sH + (size_t)code * DD + d8);
                    }
                    asm volatile("cp.async.commit_group;");
                    asm volatile("cp.async.wait_group 1;");
                } else {
                    asm volatile("cp.async.wait_group 0;");
                }
                __syncthreads();

                const unsigned b_st = uB[kc & 1] + bLaneOff;
#pragma unroll
                for (int ks = 0; ks < 4; ++ks) {       // k16 steps
                    const unsigned akoff = (unsigned)((kc * 64 + ks * 16) << 1);
                    const unsigned bkoff = (unsigned)((ks * 16) << 1);
                    unsigned ah[2][4], bh[4][2];
#pragma unroll
                    for (int mt = 0; mt < 2; ++mt)
                        ldsm_x4(ah[mt], aBase + (unsigned)(mt * 16 * APITCH * 2) + akoff);
#pragma unroll
                    for (int nt = 0; nt < 4; ++nt)
                        ldsm_x2(bh[nt], b_st + (unsigned)(nt * 8 * BPITCH * 2) + bkoff);
#pragma unroll
                    for (int mt = 0; mt < 2; ++mt)
#pragma unroll
                        for (int nt = 0; nt < 4; ++nt)
                            mma16816h(acc[mt][nt], ah[mt], bh[nt]);
                }
                __syncthreads();
            }

            // write raw c~ (scaled by 1024) to Dmat
#pragma unroll
            for (int mt = 0; mt < 2; ++mt)
#pragma unroll
                for (int h = 0; h < 2; ++h) {
                    int row = wm * 32 + mt * 16 + h * 8 + r4;
#pragma unroll
                    for (int nt = 0; nt < 4; ++nt) {
                        int col = wn * 32 + nt * 8 + 2 * kq;
                        *(float2*)(DM + row * DPITCH + col) =
                            make_float2(acc[mt][nt][h * 2], acc[mt][nt][h * 2 + 1]);
                    }
                }
            __syncthreads();

            // token threads scan 128 codes in ascending order, keep top-8
            if (tid < TILE) {
                float a_tok = Asm[tid];
                const float* dr = DM + tid * DPITCH;
#pragma unroll 4
                for (int c2 = 0; c2 < 64; ++c2) {
                    float2 cc = *(const float2*)(dr + 2 * c2);
#pragma unroll
                    for (int j = 0; j < 2; ++j) {
                        int c = 2 * c2 + j;
                        float cv = (j == 0) ? cc.x : cc.y;
                        // d = fl( fl(a+b) - 2*(c~/1024) ) ; /1024 exact
                        float dv = __fadd_rn(__fadd_rn(a_tok, E2s[c]),
                                             __fmul_rn(cv, -0.001953125f));
                        if (dv < v7) {
                            int idx = kb * 128 + c;
                            v7 = dv; i7 = idx;
                            if (v7 < v6) { float t = v6; v6 = v7; v7 = t; int ti = i6; i6 = i7; i7 = ti; }
                            if (v6 < v5) { float t = v5; v5 = v6; v6 = t; int ti = i5; i5 = i6; i6 = ti; }
                            if (v5 < v4) { float t = v4; v4 = v5; v5 = t; int ti = i4; i4 = i5; i5 = ti; }
                            if (v4 < v3) { float t = v3; v3 = v4; v4 = t; int ti = i3; i3 = i4; i4 = ti; }
                            if (v3 < v2) { float t = v2; v2 = v3; v3 = t; int ti = i2; i2 = i3; i3 = ti; }
                            if (v2 < v1) { float t = v1; v1 = v2; v2 = t; int ti = i1; i1 = i2; i2 = ti; }
                            if (v1 < v0) { float t = v0; v0 = v1; v1 = t; int ti = i0; i0 = i1; i1 = ti; }
                        }
                    }
                }
            }
            __syncthreads();
        }

        // finalize winner: sound margin; exact re-score for ambiguous tokens
        if (tid < TILE) {
            float a_tok  = Asm[tid];
            float margin = __fmaf_rn(sqrtf(a_tok), 4.0e-5f,
                           __fmaf_rn(a_tok, 5.0e-7f, 2.0e-5f));
            float thr = v0 + margin;
            int winner = i0;
            if (v1 <= thr) {
                if (v7 <= thr) {
                    // fallback (astronomically rare): exact scan of all codes
                    float best = 3.0e38f; winner = 0;
                    for (int code = 0; code < KK; ++code) {
                        const float* ev = cbl + (size_t)code * DD;
                        const float* xc = X + tid;
                        float c = 0.0f;
                        for (int d = 0; d < DD; ++d)
                            c = __fmaf_rn(xc[d * TILE], ev[d], c);
                        float dv = __fadd_rn(__fadd_rn(a_tok, g_e2[cbase + code]),
                                             __fmul_rn(-2.0f, c));
                        if (dv < best) { best = dv; winner = code; }
                    }
                } else {
                    float vv[8] = {v0, v1, v2, v3, v4, v5, v6, v7};
                    int   ii[8] = {i0, i1, i2, i3, i4, i5, i6, i7};
                    int ci[8]; int nc = 0;
#pragma unroll
                    for (int i = 0; i < 8; ++i)
                        if (vv[i] <= thr) ci[nc++] = ii[i];
                    for (int i = 1; i < nc; ++i) {      // sort ascending index
                        int key = ci[i], j = i - 1;
                        while (j >= 0 && ci[j] > key) { ci[j + 1] = ci[j]; --j; }
                        ci[j + 1] = key;
                    }
                    float best = 3.0e38f; winner = ci[0];
                    for (int cc = 0; cc < nc; ++cc) {
                        int code = ci[cc];
                        const float* ev = cbl + (size_t)code * DD;
                        const float* xc = X + tid;
                        float c = 0.0f;
#pragma unroll 8
                        for (int d = 0; d < DD; ++d)
                            c = __fmaf_rn(xc[d * TILE], ev[d], c);
                        float dv = __fadd_rn(__fadd_rn(a_tok, g_e2[cbase + code]),
                                             __fmul_rn(-2.0f, c));
                        if (dv < best) { best = dv; winner = code; }
                    }
                }
            }
            RUNI[tid] = winner;
            if (out_size > IDX_OFF) {
                size_t n = (size_t)b * TT + t0 + tid;
                size_t o = IDX_OFF + ((size_t)(l * GG + g)) * NTOK + n;
                if (o < out_size) dout[o] = (float)winner;
            }
        }
        __syncthreads();

        // residual update (reference STE elementwise)
        {
            int token = tid >> 2, dq = tid & 3;
            int code  = RUNI[token];
            const float* ev = cbl + (size_t)code * DD + dq * 64;
            float* xc = X + (dq * 64) * TILE + token;
#pragma unroll 8
            for (int dd = 0; dd < 64; ++dd) {
                float x  = xc[dd * TILE];
                float dl = __fsub_rn(ev[dd], x);
                float qn = __fadd_rn(x, dl);
                xc[dd * TILE] = __fsub_rn(x, qn);
                lacc += (double)dl * (double)dl;
            }
        }
        __syncthreads();
    }

    // quantized_out = xin - final residual
    for (int i = tid; i < DD * TILE; i += NTH) {
        int d = i >> 6, t = i & 63;
        size_t o = ((size_t)b * (GG * DD) + (size_t)g * DD + d) * TT + t0 + t;
        if (o < out_size && o < QOUT_ELEMS)
            dout[o] = __fsub_rn(xb[(size_t)d * TT + t], X[i]);
    }

    // deterministic per-CTA loss partial
    red[tid] = lacc;
    __syncthreads();
    for (int s = 128; s > 0; s >>= 1) {
        if (tid < s) red[tid] += red[tid + s];
        __syncthreads();
    }
    if (tid == 0) g_loss[blockIdx.y * 1024 + blockIdx.x] = red[0];
}

// ---------------------------------------------------------------- loss reduce
__global__ void loss_kernel(float* __restrict__ dout, unsigned long long out_size) {
    __shared__ double red[256];
    int tid = threadIdx.x;
    double s = 0.0;
    for (int i = tid; i < 2048; i += 256) s += g_loss[i];
    red[tid] = s;
    __syncthreads();
    for (int st = 128; st > 0; st >>= 1) {
        if (tid < st) red[tid] += red[tid + st];
        __syncthreads();
    }
    if (tid == 0 && out_size > LOSS_OFF)
        dout[LOSS_OFF] = (float)(1.25 * red[0] / (8.0 * 33554432.0));
}

// ---------------------------------------------------------------- launch
extern "C" void kernel_launch(void* const* d_in, const int* in_sizes, int n_in,
                              void* d_out, int out_size) {
    const float* xin = (const float*)d_in[0];
    const float* cb  = (const float*)d_in[1];
    if (n_in >= 2 && in_sizes[0] == CBELEMS) {
        xin = (const float*)d_in[1];
        cb  = (const float*)d_in[0];
    }
    float* dout = (float*)d_out;
    unsigned long long osz = (unsigned long long)out_size;

    static bool attr_set = false;
    if (!attr_set) {
        cudaFuncSetAttribute(rvq_kernel, cudaFuncAttributeMaxDynamicSharedMemorySize,
                             SMEM_TOT);
        attr_set = true;
    }

    e2_kernel<<<(LL * GG * KK + 255) / 256, 256>>>(cb);
    eh_kernel<<<(CBELEMS + 255) / 256, 256>>>(cb);
    dim3 grid(1024, GG);
    rvq_kernel<<<grid, NTH, SMEM_TOT>>>(xin, cb, dout, osz);
    loss_kernel<<<1, 256>>>(dout, osz);
}